// round 4
// baseline (speedup 1.0000x reference)
#include <cuda_runtime.h>
#include <cstdint>

#define N_USERS 40000
#define N_ITEMS 60000
#define N_NODES 100000
#define N_EDGES 1280000
#define EMB 64
#define NEG_SLOPE 0.2f
#define LDUV 68            // padded row stride (floats), 16B-aligned rows

// Scratch
__device__ float g_e[N_NODES * EMB];
__device__ float g_x[N_NODES * EMB];
__device__ int   g_deg[N_NODES];
__device__ int   g_off[N_NODES];       // exclusive row offsets (rowptr)
__device__ int   g_head[N_NODES];      // scatter cursors
__device__ int2  g_csr_cv[N_EDGES];    // packed (col, val-as-int)

// ---------------------------------------------------------------------------
// init: e = concat(user_emb, item_emb); acc (d_out) = e ; deg = 0
// ---------------------------------------------------------------------------
__global__ void k_init(const float* __restrict__ ue, const float* __restrict__ ie,
                       float* __restrict__ out) {
    int i = blockIdx.x * blockDim.x + threadIdx.x;   // float4 index
    const int total4 = N_NODES * EMB / 4;
    if (i < N_NODES) g_deg[i] = 0;
    if (i >= total4) return;
    const int user4 = N_USERS * EMB / 4;
    float4 v;
    if (i < user4) v = ((const float4*)ue)[i];
    else           v = ((const float4*)ie)[i - user4];
    ((float4*)g_e)[i] = v;
    ((float4*)out)[i] = v;
}

// ---------------------------------------------------------------------------
// CSR build: histogram -> single-block scan -> scatter
// ---------------------------------------------------------------------------
__global__ void k_hist(const int* __restrict__ erow) {
    int i = blockIdx.x * blockDim.x + threadIdx.x;
    if (i < N_EDGES) atomicAdd(&g_deg[erow[i]], 1);
}

__global__ void __launch_bounds__(1024) k_scan() {
    __shared__ int s[1024];
    const int CH = (N_NODES + 1023) / 1024;          // 98
    int t = threadIdx.x;
    int begin = t * CH;
    int end = begin + CH; if (end > N_NODES) end = N_NODES;
    int sum = 0;
    for (int i = begin; i < end; i++) sum += g_deg[i];
    s[t] = sum;
    __syncthreads();
    int inc = sum;
    #pragma unroll
    for (int d = 1; d < 1024; d <<= 1) {
        int v = (t >= d) ? s[t - d] : 0;
        __syncthreads();
        inc += v;
        s[t] = inc;
        __syncthreads();
    }
    int run = inc - sum;                              // exclusive prefix
    for (int i = begin; i < end; i++) {
        int d = g_deg[i];
        g_off[i] = run;
        g_head[i] = run;
        run += d;
    }
}

__global__ void k_scatter(const int* __restrict__ erow, const int* __restrict__ ecol,
                          const float* __restrict__ eval) {
    int i = blockIdx.x * blockDim.x + threadIdx.x;
    if (i >= N_EDGES) return;
    int r = erow[i];
    int pos = atomicAdd(&g_head[r], 1);
    g_csr_cv[pos] = make_int2(ecol[i], __float_as_int(eval[i]));
}

// ---------------------------------------------------------------------------
// CSR SpMM (gather, no atomics): x[n] = sum_j val_j * e[col_j]
// 16 threads per node; thread c owns float4 chunk c.
// ---------------------------------------------------------------------------
__global__ void __launch_bounds__(256) k_spmm_csr() {
    int t = blockIdx.x * blockDim.x + threadIdx.x;
    int node = t >> 4;
    int c = t & 15;
    if (node >= N_NODES) return;
    int start = g_off[node];
    int deg = g_deg[node];

    float4 a0 = make_float4(0.f, 0.f, 0.f, 0.f);
    float4 a1 = make_float4(0.f, 0.f, 0.f, 0.f);
    int j = 0;
    for (; j + 1 < deg; j += 2) {
        int2 cv0 = g_csr_cv[start + j];
        int2 cv1 = g_csr_cv[start + j + 1];
        float v0 = __int_as_float(cv0.y);
        float v1 = __int_as_float(cv1.y);
        float4 f0 = __ldg(((const float4*)g_e) + cv0.x * 16 + c);
        float4 f1 = __ldg(((const float4*)g_e) + cv1.x * 16 + c);
        a0.x += v0 * f0.x; a0.y += v0 * f0.y; a0.z += v0 * f0.z; a0.w += v0 * f0.w;
        a1.x += v1 * f1.x; a1.y += v1 * f1.y; a1.z += v1 * f1.z; a1.w += v1 * f1.w;
    }
    if (j < deg) {
        int2 cv0 = g_csr_cv[start + j];
        float v0 = __int_as_float(cv0.y);
        float4 f0 = __ldg(((const float4*)g_e) + cv0.x * 16 + c);
        a0.x += v0 * f0.x; a0.y += v0 * f0.y; a0.z += v0 * f0.z; a0.w += v0 * f0.w;
    }
    a0.x += a1.x; a0.y += a1.y; a0.z += a1.z; a0.w += a1.w;
    ((float4*)g_x)[node * 16 + c] = a0;
}

// ---------------------------------------------------------------------------
// Dense layer: h = (e+x)@W1 + (x*e)@W2 + b ; lrelu ; l2norm -> e ;
//   out = (out + e) * scale
// 64 nodes x 64 cols per block, 256 threads; u loaded as LDS.128 (pad 68).
// ---------------------------------------------------------------------------
__global__ void __launch_bounds__(256) k_dense(
    const float* __restrict__ W1, const float* __restrict__ b1,
    const float* __restrict__ W2, const float* __restrict__ b2,
    float* __restrict__ out, float scale) {

    __shared__ float sW[64][64];       // 16 KB
    __shared__ float sUV[64][LDUV];    // 17.4 KB, rows 16B-aligned

    const int tid = threadIdx.x;
    const int tx = tid & 15;
    const int ty = tid >> 4;
    const int base = blockIdx.x * 64;

    float acc[4][4];
    #pragma unroll
    for (int a = 0; a < 4; a++)
        #pragma unroll
        for (int j = 0; j < 4; j++) acc[a][j] = 0.f;

    #pragma unroll
    for (int ph = 0; ph < 2; ph++) {
        if (ph) __syncthreads();
        const float* W = ph ? W2 : W1;

        #pragma unroll
        for (int it = 0; it < 4; it++) {
            int i = tid + it * 256;
            ((float4*)&sW[0][0])[i] = ((const float4*)W)[i];
        }

        #pragma unroll
        for (int it = 0; it < 4; it++) {
            int i = tid + it * 256;
            int nd = i >> 4;
            int c4 = i & 15;
            int node = base + nd;
            float4 ev = make_float4(0.f, 0.f, 0.f, 0.f);
            float4 xv = make_float4(0.f, 0.f, 0.f, 0.f);
            if (node < N_NODES) {
                ev = ((const float4*)g_e)[node * 16 + c4];
                xv = ((const float4*)g_x)[node * 16 + c4];
            }
            float4 u;
            if (ph == 0) {
                u = make_float4(ev.x + xv.x, ev.y + xv.y, ev.z + xv.z, ev.w + xv.w);
            } else {
                u = make_float4(ev.x * xv.x, ev.y * xv.y, ev.z * xv.z, ev.w * xv.w);
            }
            sUV[c4 * 4 + 0][nd] = u.x;
            sUV[c4 * 4 + 1][nd] = u.y;
            sUV[c4 * 4 + 2][nd] = u.z;
            sUV[c4 * 4 + 3][nd] = u.w;
        }
        __syncthreads();

        #pragma unroll 16
        for (int k = 0; k < 64; k++) {
            float4 w = *(const float4*)&sW[k][tx * 4];
            float4 u = *(const float4*)&sUV[k][ty * 4];
            acc[0][0] += u.x * w.x; acc[0][1] += u.x * w.y; acc[0][2] += u.x * w.z; acc[0][3] += u.x * w.w;
            acc[1][0] += u.y * w.x; acc[1][1] += u.y * w.y; acc[1][2] += u.y * w.z; acc[1][3] += u.y * w.w;
            acc[2][0] += u.z * w.x; acc[2][1] += u.z * w.y; acc[2][2] += u.z * w.z; acc[2][3] += u.z * w.w;
            acc[3][0] += u.w * w.x; acc[3][1] += u.w * w.y; acc[3][2] += u.w * w.z; acc[3][3] += u.w * w.w;
        }
    }

    const int j0 = tx * 4;
    float bb0 = b1[j0 + 0] + b2[j0 + 0];
    float bb1 = b1[j0 + 1] + b2[j0 + 1];
    float bb2 = b1[j0 + 2] + b2[j0 + 2];
    float bb3 = b1[j0 + 3] + b2[j0 + 3];

    #pragma unroll
    for (int a = 0; a < 4; a++) {
        float h0 = acc[a][0] + bb0;
        float h1 = acc[a][1] + bb1;
        float h2 = acc[a][2] + bb2;
        float h3 = acc[a][3] + bb3;
        h0 = (h0 >= 0.f) ? h0 : NEG_SLOPE * h0;
        h1 = (h1 >= 0.f) ? h1 : NEG_SLOPE * h1;
        h2 = (h2 >= 0.f) ? h2 : NEG_SLOPE * h2;
        h3 = (h3 >= 0.f) ? h3 : NEG_SLOPE * h3;
        float ss = h0 * h0 + h1 * h1 + h2 * h2 + h3 * h3;
        ss += __shfl_xor_sync(0xffffffffu, ss, 1);
        ss += __shfl_xor_sync(0xffffffffu, ss, 2);
        ss += __shfl_xor_sync(0xffffffffu, ss, 4);
        ss += __shfl_xor_sync(0xffffffffu, ss, 8);
        float inv = rsqrtf(fmaxf(ss, 1e-24f));
        float e0 = h0 * inv, e1 = h1 * inv, e2 = h2 * inv, e3 = h3 * inv;

        int node = base + ty * 4 + a;
        if (node < N_NODES) {
            ((float4*)g_e)[node * 16 + tx] = make_float4(e0, e1, e2, e3);
            float4 o = ((float4*)out)[node * 16 + tx];
            o.x = (o.x + e0) * scale;
            o.y = (o.y + e1) * scale;
            o.z = (o.z + e2) * scale;
            o.w = (o.w + e3) * scale;
            ((float4*)out)[node * 16 + tx] = o;
        }
    }
}

// ---------------------------------------------------------------------------
extern "C" void kernel_launch(void* const* d_in, const int* in_sizes, int n_in,
                              void* d_out, int out_size) {
    const int*   erow = (const int*)d_in[0];
    const int*   ecol = (const int*)d_in[1];
    const float* eval = (const float*)d_in[2];
    const float* ue   = (const float*)d_in[3];
    const float* ie   = (const float*)d_in[4];
    const float* W1   = (const float*)d_in[5];
    const float* b1   = (const float*)d_in[6];
    const float* W2   = (const float*)d_in[7];
    const float* b2   = (const float*)d_in[8];
    float* out = (float*)d_out;

    const int total4 = N_NODES * EMB / 4;                   // 1.6M
    const int init_blocks = (total4 + 255) / 256;           // 6250
    const int edge_blocks = (N_EDGES + 255) / 256;          // 5000
    const int spmm_blocks = (N_NODES * 16 + 255) / 256;     // 6250
    const int dense_blocks = (N_NODES + 63) / 64;           // 1563

    k_init<<<init_blocks, 256>>>(ue, ie, out);
    k_hist<<<edge_blocks, 256>>>(erow);
    k_scan<<<1, 1024>>>();
    k_scatter<<<edge_blocks, 256>>>(erow, ecol, eval);

    for (int l = 0; l < 3; l++) {
        k_spmm_csr<<<spmm_blocks, 256>>>();
        float scale = (l == 2) ? 0.25f : 1.0f;
        k_dense<<<dense_blocks, 256>>>(W1 + l * EMB * EMB, b1 + l * EMB,
                                       W2 + l * EMB * EMB, b2 + l * EMB,
                                       out, scale);
    }
}

// round 5
// speedup vs baseline: 1.0238x; 1.0238x over previous
#include <cuda_runtime.h>
#include <cstdint>

#define N_USERS 40000
#define N_ITEMS 60000
#define N_NODES 100000
#define N_EDGES 1280000
#define EMB 64
#define NEG_SLOPE 0.2f

// Scratch
__device__ float g_e[N_NODES * EMB];
__device__ float g_x[N_NODES * EMB];
__device__ int   g_deg[N_NODES];
__device__ int   g_off[N_NODES];       // exclusive row offsets (rowptr)
__device__ int   g_head[N_NODES];      // scatter cursors
__device__ int2  g_csr_cv[N_EDGES];    // packed (col, val-as-int)

// ---------------------------------------------------------------------------
// init: e = concat(user_emb, item_emb); acc (d_out) = e ; deg = 0
// ---------------------------------------------------------------------------
__global__ void k_init(const float* __restrict__ ue, const float* __restrict__ ie,
                       float* __restrict__ out) {
    int i = blockIdx.x * blockDim.x + threadIdx.x;   // float4 index
    const int total4 = N_NODES * EMB / 4;
    if (i < N_NODES) g_deg[i] = 0;
    if (i >= total4) return;
    const int user4 = N_USERS * EMB / 4;
    float4 v;
    if (i < user4) v = ((const float4*)ue)[i];
    else           v = ((const float4*)ie)[i - user4];
    ((float4*)g_e)[i] = v;
    ((float4*)out)[i] = v;
}

// ---------------------------------------------------------------------------
// CSR build: histogram -> single-block scan -> scatter
// ---------------------------------------------------------------------------
__global__ void k_hist(const int* __restrict__ erow) {
    int base = blockIdx.x * (blockDim.x * 4) + threadIdx.x;
    #pragma unroll
    for (int u = 0; u < 4; u++) {
        int i = base + u * blockDim.x;
        if (i < N_EDGES) atomicAdd(&g_deg[erow[i]], 1);
    }
}

__global__ void __launch_bounds__(1024) k_scan() {
    __shared__ int s[1024];
    const int CH = (N_NODES + 1023) / 1024;          // 98
    int t = threadIdx.x;
    int begin = t * CH;
    int end = begin + CH; if (end > N_NODES) end = N_NODES;
    int sum = 0;
    for (int i = begin; i < end; i++) sum += g_deg[i];
    s[t] = sum;
    __syncthreads();
    int inc = sum;
    #pragma unroll
    for (int d = 1; d < 1024; d <<= 1) {
        int v = (t >= d) ? s[t - d] : 0;
        __syncthreads();
        inc += v;
        s[t] = inc;
        __syncthreads();
    }
    int run = inc - sum;                              // exclusive prefix
    for (int i = begin; i < end; i++) {
        int d = g_deg[i];
        g_off[i] = run;
        g_head[i] = run;
        run += d;
    }
}

__global__ void k_scatter(const int* __restrict__ erow, const int* __restrict__ ecol,
                          const float* __restrict__ eval) {
    int base = blockIdx.x * (blockDim.x * 4) + threadIdx.x;
    int idx[4], row[4];
    int cnt = 0;
    #pragma unroll
    for (int u = 0; u < 4; u++) {
        int i = base + u * blockDim.x;
        if (i < N_EDGES) { idx[cnt] = i; row[cnt] = erow[i]; cnt++; }
    }
    int pos[4];
    #pragma unroll
    for (int u = 0; u < 4; u++)
        if (u < cnt) pos[u] = atomicAdd(&g_head[row[u]], 1);
    #pragma unroll
    for (int u = 0; u < 4; u++)
        if (u < cnt)
            g_csr_cv[pos[u]] = make_int2(ecol[idx[u]], __float_as_int(eval[idx[u]]));
}

// ---------------------------------------------------------------------------
// CSR SpMM (gather, no atomics): x[n] = sum_j val_j * e[col_j]
// 16 threads per node; thread c owns float4 chunk c.
// ---------------------------------------------------------------------------
__global__ void __launch_bounds__(256) k_spmm_csr() {
    int t = blockIdx.x * blockDim.x + threadIdx.x;
    int node = t >> 4;
    int c = t & 15;
    if (node >= N_NODES) return;
    int start = g_off[node];
    int deg = g_deg[node];

    float4 a0 = make_float4(0.f, 0.f, 0.f, 0.f);
    float4 a1 = make_float4(0.f, 0.f, 0.f, 0.f);
    int j = 0;
    for (; j + 1 < deg; j += 2) {
        int2 cv0 = g_csr_cv[start + j];
        int2 cv1 = g_csr_cv[start + j + 1];
        float v0 = __int_as_float(cv0.y);
        float v1 = __int_as_float(cv1.y);
        float4 f0 = __ldg(((const float4*)g_e) + cv0.x * 16 + c);
        float4 f1 = __ldg(((const float4*)g_e) + cv1.x * 16 + c);
        a0.x += v0 * f0.x; a0.y += v0 * f0.y; a0.z += v0 * f0.z; a0.w += v0 * f0.w;
        a1.x += v1 * f1.x; a1.y += v1 * f1.y; a1.z += v1 * f1.z; a1.w += v1 * f1.w;
    }
    if (j < deg) {
        int2 cv0 = g_csr_cv[start + j];
        float v0 = __int_as_float(cv0.y);
        float4 f0 = __ldg(((const float4*)g_e) + cv0.x * 16 + c);
        a0.x += v0 * f0.x; a0.y += v0 * f0.y; a0.z += v0 * f0.z; a0.w += v0 * f0.w;
    }
    a0.x += a1.x; a0.y += a1.y; a0.z += a1.z; a0.w += a1.w;
    ((float4*)g_x)[node * 16 + c] = a0;
}

// ---------------------------------------------------------------------------
// Dense layer (exact round-3 kernel, regs=63, no spills):
// h = (e+x)@W1 + (x*e)@W2 + b ; lrelu ; l2norm -> e ; out = (out+e)*scale
// ---------------------------------------------------------------------------
__global__ void __launch_bounds__(256) k_dense(
    const float* __restrict__ W1, const float* __restrict__ b1,
    const float* __restrict__ W2, const float* __restrict__ b2,
    float* __restrict__ out, float scale) {

    __shared__ float sW[64][64];
    __shared__ float sUV[64][67];

    const int tid = threadIdx.x;
    const int tx = tid & 15;
    const int ty = tid >> 4;
    const int base = blockIdx.x * 64;

    float acc[4][4];
    #pragma unroll
    for (int a = 0; a < 4; a++)
        #pragma unroll
        for (int j = 0; j < 4; j++) acc[a][j] = 0.f;

    #pragma unroll
    for (int ph = 0; ph < 2; ph++) {
        if (ph) __syncthreads();
        const float* W = ph ? W2 : W1;

        #pragma unroll
        for (int it = 0; it < 4; it++) {
            int i = tid + it * 256;
            ((float4*)&sW[0][0])[i] = ((const float4*)W)[i];
        }

        #pragma unroll
        for (int it = 0; it < 4; it++) {
            int i = tid + it * 256;
            int nd = i >> 4;
            int c4 = i & 15;
            int node = base + nd;
            float4 ev = make_float4(0.f, 0.f, 0.f, 0.f);
            float4 xv = make_float4(0.f, 0.f, 0.f, 0.f);
            if (node < N_NODES) {
                ev = ((const float4*)g_e)[node * 16 + c4];
                xv = ((const float4*)g_x)[node * 16 + c4];
            }
            float4 u;
            if (ph == 0) {
                u = make_float4(ev.x + xv.x, ev.y + xv.y, ev.z + xv.z, ev.w + xv.w);
            } else {
                u = make_float4(ev.x * xv.x, ev.y * xv.y, ev.z * xv.z, ev.w * xv.w);
            }
            sUV[c4 * 4 + 0][nd] = u.x;
            sUV[c4 * 4 + 1][nd] = u.y;
            sUV[c4 * 4 + 2][nd] = u.z;
            sUV[c4 * 4 + 3][nd] = u.w;
        }
        __syncthreads();

        #pragma unroll 16
        for (int k = 0; k < 64; k++) {
            float4 w = *(const float4*)&sW[k][tx * 4];
            float u0 = sUV[k][ty * 4 + 0];
            float u1 = sUV[k][ty * 4 + 1];
            float u2 = sUV[k][ty * 4 + 2];
            float u3 = sUV[k][ty * 4 + 3];
            acc[0][0] += u0 * w.x; acc[0][1] += u0 * w.y; acc[0][2] += u0 * w.z; acc[0][3] += u0 * w.w;
            acc[1][0] += u1 * w.x; acc[1][1] += u1 * w.y; acc[1][2] += u1 * w.z; acc[1][3] += u1 * w.w;
            acc[2][0] += u2 * w.x; acc[2][1] += u2 * w.y; acc[2][2] += u2 * w.z; acc[2][3] += u2 * w.w;
            acc[3][0] += u3 * w.x; acc[3][1] += u3 * w.y; acc[3][2] += u3 * w.z; acc[3][3] += u3 * w.w;
        }
    }

    const int j0 = tx * 4;
    float bb0 = b1[j0 + 0] + b2[j0 + 0];
    float bb1 = b1[j0 + 1] + b2[j0 + 1];
    float bb2 = b1[j0 + 2] + b2[j0 + 2];
    float bb3 = b1[j0 + 3] + b2[j0 + 3];

    #pragma unroll
    for (int a = 0; a < 4; a++) {
        float h0 = acc[a][0] + bb0;
        float h1 = acc[a][1] + bb1;
        float h2 = acc[a][2] + bb2;
        float h3 = acc[a][3] + bb3;
        h0 = (h0 >= 0.f) ? h0 : NEG_SLOPE * h0;
        h1 = (h1 >= 0.f) ? h1 : NEG_SLOPE * h1;
        h2 = (h2 >= 0.f) ? h2 : NEG_SLOPE * h2;
        h3 = (h3 >= 0.f) ? h3 : NEG_SLOPE * h3;
        float ss = h0 * h0 + h1 * h1 + h2 * h2 + h3 * h3;
        ss += __shfl_xor_sync(0xffffffffu, ss, 1);
        ss += __shfl_xor_sync(0xffffffffu, ss, 2);
        ss += __shfl_xor_sync(0xffffffffu, ss, 4);
        ss += __shfl_xor_sync(0xffffffffu, ss, 8);
        float inv = rsqrtf(fmaxf(ss, 1e-24f));
        float e0 = h0 * inv, e1 = h1 * inv, e2 = h2 * inv, e3 = h3 * inv;

        int node = base + ty * 4 + a;
        if (node < N_NODES) {
            ((float4*)g_e)[node * 16 + tx] = make_float4(e0, e1, e2, e3);
            float4 o = ((float4*)out)[node * 16 + tx];
            o.x = (o.x + e0) * scale;
            o.y = (o.y + e1) * scale;
            o.z = (o.z + e2) * scale;
            o.w = (o.w + e3) * scale;
            ((float4*)out)[node * 16 + tx] = o;
        }
    }
}

// ---------------------------------------------------------------------------
extern "C" void kernel_launch(void* const* d_in, const int* in_sizes, int n_in,
                              void* d_out, int out_size) {
    const int*   erow = (const int*)d_in[0];
    const int*   ecol = (const int*)d_in[1];
    const float* eval = (const float*)d_in[2];
    const float* ue   = (const float*)d_in[3];
    const float* ie   = (const float*)d_in[4];
    const float* W1   = (const float*)d_in[5];
    const float* b1   = (const float*)d_in[6];
    const float* W2   = (const float*)d_in[7];
    const float* b2   = (const float*)d_in[8];
    float* out = (float*)d_out;

    const int total4 = N_NODES * EMB / 4;                   // 1.6M
    const int init_blocks = (total4 + 255) / 256;           // 6250
    const int edge4_blocks = (N_EDGES + 1023) / 1024;       // 1250
    const int spmm_blocks = (N_NODES * 16 + 255) / 256;     // 6250
    const int dense_blocks = (N_NODES + 63) / 64;           // 1563

    k_init<<<init_blocks, 256>>>(ue, ie, out);
    k_hist<<<edge4_blocks, 256>>>(erow);
    k_scan<<<1, 1024>>>();
    k_scatter<<<edge4_blocks, 256>>>(erow, ecol, eval);

    for (int l = 0; l < 3; l++) {
        k_spmm_csr<<<spmm_blocks, 256>>>();
        float scale = (l == 2) ? 0.25f : 1.0f;
        k_dense<<<dense_blocks, 256>>>(W1 + l * EMB * EMB, b1 + l * EMB,
                                       W2 + l * EMB * EMB, b2 + l * EMB,
                                       out, scale);
    }
}

// round 6
// speedup vs baseline: 1.5094x; 1.4742x over previous
#include <cuda_runtime.h>
#include <cstdint>

#define N_USERS 40000
#define N_ITEMS 60000
#define N_NODES 100000
#define N_EDGES 1280000
#define EMB 64
#define NEG_SLOPE 0.2f

#define SCAN_BLK 1024
#define NSCAN_BLOCKS ((N_NODES + SCAN_BLK - 1) / SCAN_BLK)   // 98

// Scratch
__device__ float g_e[N_NODES * EMB];
__device__ float g_x[N_NODES * EMB];
__device__ int   g_deg[N_NODES];
__device__ int   g_off[N_NODES];       // exclusive row offsets (rowptr)
__device__ int   g_head[N_NODES];      // scatter cursors
__device__ int   g_bsum[NSCAN_BLOCKS];
__device__ int2  g_csr_cv[N_EDGES];    // packed (col, val-as-int)

// ---------------------------------------------------------------------------
// init: e = concat(user_emb, item_emb); acc (d_out) = e ; deg = 0
// ---------------------------------------------------------------------------
__global__ void k_init(const float* __restrict__ ue, const float* __restrict__ ie,
                       float* __restrict__ out) {
    int i = blockIdx.x * blockDim.x + threadIdx.x;   // float4 index
    const int total4 = N_NODES * EMB / 4;
    if (i < N_NODES) g_deg[i] = 0;
    if (i >= total4) return;
    const int user4 = N_USERS * EMB / 4;
    float4 v;
    if (i < user4) v = ((const float4*)ue)[i];
    else           v = ((const float4*)ie)[i - user4];
    ((float4*)g_e)[i] = v;
    ((float4*)out)[i] = v;
}

// ---------------------------------------------------------------------------
// CSR build (exact round-3 path: hist -> scanA/B/C -> scatter)
// ---------------------------------------------------------------------------
__global__ void k_hist(const int* __restrict__ erow) {
    int i = blockIdx.x * blockDim.x + threadIdx.x;
    if (i < N_EDGES) atomicAdd(&g_deg[erow[i]], 1);
}

__global__ void __launch_bounds__(SCAN_BLK) k_scanA() {
    __shared__ int s[SCAN_BLK];
    int i = blockIdx.x * SCAN_BLK + threadIdx.x;
    int v = (i < N_NODES) ? g_deg[i] : 0;
    s[threadIdx.x] = v;
    __syncthreads();
    int inc = v;
    #pragma unroll
    for (int d = 1; d < SCAN_BLK; d <<= 1) {
        int t = (threadIdx.x >= d) ? s[threadIdx.x - d] : 0;
        __syncthreads();
        inc += t;
        s[threadIdx.x] = inc;
        __syncthreads();
    }
    if (i < N_NODES) g_off[i] = inc - v;          // exclusive within block
    if (threadIdx.x == SCAN_BLK - 1) g_bsum[blockIdx.x] = inc;
}

__global__ void k_scanB() {
    if (threadIdx.x == 0) {
        int run = 0;
        for (int b = 0; b < NSCAN_BLOCKS; b++) {
            int v = g_bsum[b];
            g_bsum[b] = run;
            run += v;
        }
    }
}

__global__ void k_scanC() {
    int i = blockIdx.x * blockDim.x + threadIdx.x;
    if (i >= N_NODES) return;
    int o = g_off[i] + g_bsum[i / SCAN_BLK];
    g_off[i] = o;
    g_head[i] = o;
}

__global__ void k_scatter(const int* __restrict__ erow, const int* __restrict__ ecol,
                          const float* __restrict__ eval) {
    int i = blockIdx.x * blockDim.x + threadIdx.x;
    if (i >= N_EDGES) return;
    int r = erow[i];
    int pos = atomicAdd(&g_head[r], 1);
    g_csr_cv[pos] = make_int2(ecol[i], __float_as_int(eval[i]));
}

// ---------------------------------------------------------------------------
// CSR SpMM (gather, no atomics): x[n] = sum_j val_j * e[col_j]
// 16 threads per node; thread c owns float4 chunk c. Edge loop unrolled x4.
// ---------------------------------------------------------------------------
__global__ void __launch_bounds__(256) k_spmm_csr() {
    int t = blockIdx.x * blockDim.x + threadIdx.x;
    int node = t >> 4;
    int c = t & 15;
    if (node >= N_NODES) return;
    int start = g_off[node];
    int deg = g_deg[node];

    float4 a0 = make_float4(0.f, 0.f, 0.f, 0.f);
    float4 a1 = make_float4(0.f, 0.f, 0.f, 0.f);
    int j = 0;
    for (; j + 3 < deg; j += 4) {
        int2 cv0 = g_csr_cv[start + j];
        int2 cv1 = g_csr_cv[start + j + 1];
        int2 cv2 = g_csr_cv[start + j + 2];
        int2 cv3 = g_csr_cv[start + j + 3];
        float4 f0 = __ldg(((const float4*)g_e) + cv0.x * 16 + c);
        float4 f1 = __ldg(((const float4*)g_e) + cv1.x * 16 + c);
        float4 f2 = __ldg(((const float4*)g_e) + cv2.x * 16 + c);
        float4 f3 = __ldg(((const float4*)g_e) + cv3.x * 16 + c);
        float v0 = __int_as_float(cv0.y);
        float v1 = __int_as_float(cv1.y);
        float v2 = __int_as_float(cv2.y);
        float v3 = __int_as_float(cv3.y);
        a0.x += v0 * f0.x; a0.y += v0 * f0.y; a0.z += v0 * f0.z; a0.w += v0 * f0.w;
        a1.x += v1 * f1.x; a1.y += v1 * f1.y; a1.z += v1 * f1.z; a1.w += v1 * f1.w;
        a0.x += v2 * f2.x; a0.y += v2 * f2.y; a0.z += v2 * f2.z; a0.w += v2 * f2.w;
        a1.x += v3 * f3.x; a1.y += v3 * f3.y; a1.z += v3 * f3.z; a1.w += v3 * f3.w;
    }
    for (; j < deg; j++) {
        int2 cv0 = g_csr_cv[start + j];
        float v0 = __int_as_float(cv0.y);
        float4 f0 = __ldg(((const float4*)g_e) + cv0.x * 16 + c);
        a0.x += v0 * f0.x; a0.y += v0 * f0.y; a0.z += v0 * f0.z; a0.w += v0 * f0.w;
    }
    a0.x += a1.x; a0.y += a1.y; a0.z += a1.z; a0.w += a1.w;
    ((float4*)g_x)[node * 16 + c] = a0;
}

// ---------------------------------------------------------------------------
// Dense layer (exact round-3 kernel): h = (e+x)@W1 + (x*e)@W2 + b ; lrelu ;
//   l2norm -> e ; out = (out + e) * scale
// ---------------------------------------------------------------------------
__global__ void __launch_bounds__(256) k_dense(
    const float* __restrict__ W1, const float* __restrict__ b1,
    const float* __restrict__ W2, const float* __restrict__ b2,
    float* __restrict__ out, float scale) {

    __shared__ float sW[64][64];
    __shared__ float sUV[64][67];

    const int tid = threadIdx.x;
    const int tx = tid & 15;
    const int ty = tid >> 4;
    const int base = blockIdx.x * 64;

    float acc[4][4];
    #pragma unroll
    for (int a = 0; a < 4; a++)
        #pragma unroll
        for (int j = 0; j < 4; j++) acc[a][j] = 0.f;

    #pragma unroll
    for (int ph = 0; ph < 2; ph++) {
        if (ph) __syncthreads();
        const float* W = ph ? W2 : W1;

        #pragma unroll
        for (int it = 0; it < 4; it++) {
            int i = tid + it * 256;
            ((float4*)&sW[0][0])[i] = ((const float4*)W)[i];
        }

        #pragma unroll
        for (int it = 0; it < 4; it++) {
            int i = tid + it * 256;
            int nd = i >> 4;
            int c4 = i & 15;
            int node = base + nd;
            float4 ev = make_float4(0.f, 0.f, 0.f, 0.f);
            float4 xv = make_float4(0.f, 0.f, 0.f, 0.f);
            if (node < N_NODES) {
                ev = ((const float4*)g_e)[node * 16 + c4];
                xv = ((const float4*)g_x)[node * 16 + c4];
            }
            float4 u;
            if (ph == 0) {
                u = make_float4(ev.x + xv.x, ev.y + xv.y, ev.z + xv.z, ev.w + xv.w);
            } else {
                u = make_float4(ev.x * xv.x, ev.y * xv.y, ev.z * xv.z, ev.w * xv.w);
            }
            sUV[c4 * 4 + 0][nd] = u.x;
            sUV[c4 * 4 + 1][nd] = u.y;
            sUV[c4 * 4 + 2][nd] = u.z;
            sUV[c4 * 4 + 3][nd] = u.w;
        }
        __syncthreads();

        #pragma unroll 16
        for (int k = 0; k < 64; k++) {
            float4 w = *(const float4*)&sW[k][tx * 4];
            float u0 = sUV[k][ty * 4 + 0];
            float u1 = sUV[k][ty * 4 + 1];
            float u2 = sUV[k][ty * 4 + 2];
            float u3 = sUV[k][ty * 4 + 3];
            acc[0][0] += u0 * w.x; acc[0][1] += u0 * w.y; acc[0][2] += u0 * w.z; acc[0][3] += u0 * w.w;
            acc[1][0] += u1 * w.x; acc[1][1] += u1 * w.y; acc[1][2] += u1 * w.z; acc[1][3] += u1 * w.w;
            acc[2][0] += u2 * w.x; acc[2][1] += u2 * w.y; acc[2][2] += u2 * w.z; acc[2][3] += u2 * w.w;
            acc[3][0] += u3 * w.x; acc[3][1] += u3 * w.y; acc[3][2] += u3 * w.z; acc[3][3] += u3 * w.w;
        }
    }

    const int j0 = tx * 4;
    float bb0 = b1[j0 + 0] + b2[j0 + 0];
    float bb1 = b1[j0 + 1] + b2[j0 + 1];
    float bb2 = b1[j0 + 2] + b2[j0 + 2];
    float bb3 = b1[j0 + 3] + b2[j0 + 3];

    #pragma unroll
    for (int a = 0; a < 4; a++) {
        float h0 = acc[a][0] + bb0;
        float h1 = acc[a][1] + bb1;
        float h2 = acc[a][2] + bb2;
        float h3 = acc[a][3] + bb3;
        h0 = (h0 >= 0.f) ? h0 : NEG_SLOPE * h0;
        h1 = (h1 >= 0.f) ? h1 : NEG_SLOPE * h1;
        h2 = (h2 >= 0.f) ? h2 : NEG_SLOPE * h2;
        h3 = (h3 >= 0.f) ? h3 : NEG_SLOPE * h3;
        float ss = h0 * h0 + h1 * h1 + h2 * h2 + h3 * h3;
        ss += __shfl_xor_sync(0xffffffffu, ss, 1);
        ss += __shfl_xor_sync(0xffffffffu, ss, 2);
        ss += __shfl_xor_sync(0xffffffffu, ss, 4);
        ss += __shfl_xor_sync(0xffffffffu, ss, 8);
        float inv = rsqrtf(fmaxf(ss, 1e-24f));
        float e0 = h0 * inv, e1 = h1 * inv, e2 = h2 * inv, e3 = h3 * inv;

        int node = base + ty * 4 + a;
        if (node < N_NODES) {
            ((float4*)g_e)[node * 16 + tx] = make_float4(e0, e1, e2, e3);
            float4 o = ((float4*)out)[node * 16 + tx];
            o.x = (o.x + e0) * scale;
            o.y = (o.y + e1) * scale;
            o.z = (o.z + e2) * scale;
            o.w = (o.w + e3) * scale;
            ((float4*)out)[node * 16 + tx] = o;
        }
    }
}

// ---------------------------------------------------------------------------
extern "C" void kernel_launch(void* const* d_in, const int* in_sizes, int n_in,
                              void* d_out, int out_size) {
    const int*   erow = (const int*)d_in[0];
    const int*   ecol = (const int*)d_in[1];
    const float* eval = (const float*)d_in[2];
    const float* ue   = (const float*)d_in[3];
    const float* ie   = (const float*)d_in[4];
    const float* W1   = (const float*)d_in[5];
    const float* b1   = (const float*)d_in[6];
    const float* W2   = (const float*)d_in[7];
    const float* b2   = (const float*)d_in[8];
    float* out = (float*)d_out;

    const int total4 = N_NODES * EMB / 4;                   // 1.6M
    const int init_blocks = (total4 + 255) / 256;           // 6250
    const int edge_blocks = (N_EDGES + 255) / 256;          // 5000
    const int node_blocks = (N_NODES + 255) / 256;          // 391
    const int spmm_blocks = (N_NODES * 16 + 255) / 256;     // 6250
    const int dense_blocks = (N_NODES + 63) / 64;           // 1563

    k_init<<<init_blocks, 256>>>(ue, ie, out);
    k_hist<<<edge_blocks, 256>>>(erow);
    k_scanA<<<NSCAN_BLOCKS, SCAN_BLK>>>();
    k_scanB<<<1, 32>>>();
    k_scanC<<<node_blocks, 256>>>();
    k_scatter<<<edge_blocks, 256>>>(erow, ecol, eval);

    for (int l = 0; l < 3; l++) {
        k_spmm_csr<<<spmm_blocks, 256>>>();
        float scale = (l == 2) ? 0.25f : 1.0f;
        k_dense<<<dense_blocks, 256>>>(W1 + l * EMB * EMB, b1 + l * EMB,
                                       W2 + l * EMB * EMB, b2 + l * EMB,
                                       out, scale);
    }
}